// round 15
// baseline (speedup 1.0000x reference)
#include <cuda_runtime.h>
#include <math.h>

// ---------------- problem constants ----------------
#define SEQ   256
#define BATCH 2
#define HIDD  512
#define NHEAD 8
#define HDIM  64
#define NROW  512              // BATCH*SEQ
#define CHB   2048             // chunks per batch = SEQ*NHEAD
#define EPSN  1e-15f
#define MAXNORM 0.996f         // (1-4e-3)/sqrt(c), c=1

// ---------------- device scratch (static, allowed) ----------------
__device__ float g_mx[3 * NROW * HIDD];        // GEMM outputs (3 MB)
__device__ float g_q[NROW * HIDD];             // ql chunks, flat [b][s'][512]
__device__ float g_k[NROW * HIDD];
__device__ float g_v[NROW * HIDD];
__device__ float g_q2[BATCH * CHB];            // |ql chunk|^2
__device__ float g_k2[BATCH * CHB];
__device__ float g_gamma[BATCH * CHB];         // 2/max(1-|vl|^2,eps)
__device__ float g_pnom[4 * NROW * HIDD];      // ctx partial numerators (4 MB)
__device__ float g_pdac[4 * NROW * NHEAD];     // ctx partial denominators
__device__ float g_probs[BATCH * NHEAD * SEQ * SEQ]; // fallback if out lacks probs
// tf32 hi/lo planes: A (query, rows pre-permuted to r=b*256+s'), B (Wq|Wk|Wv as [n][k])
__device__ float g_ah[NROW * HIDD];
__device__ float g_al[NROW * HIDD];
__device__ float g_bh[3 * HIDD * HIDD];
__device__ float g_bl[3 * HIDD * HIDD];

// ---------------- packed f32x2 helpers ----------------
__device__ __forceinline__ float2 ffma2(float2 a, float2 b, float2 c) {
    unsigned long long ua = *(unsigned long long*)&a;
    unsigned long long ub = *(unsigned long long*)&b;
    unsigned long long uc = *(unsigned long long*)&c;
    unsigned long long ud;
    asm("fma.rn.f32x2 %0, %1, %2, %3;" : "=l"(ud) : "l"(ua), "l"(ub), "l"(uc));
    return *(float2*)&ud;
}
__device__ __forceinline__ float2 fmul2(float2 a, float2 b) {
    unsigned long long ua = *(unsigned long long*)&a;
    unsigned long long ub = *(unsigned long long*)&b;
    unsigned long long ud;
    asm("mul.rn.f32x2 %0, %1, %2;" : "=l"(ud) : "l"(ua), "l"(ub));
    return *(float2*)&ud;
}
__device__ __forceinline__ float2 fadd2(float2 a, float2 b) {
    unsigned long long ua = *(unsigned long long*)&a;
    unsigned long long ub = *(unsigned long long*)&b;
    unsigned long long ud;
    asm("add.rn.f32x2 %0, %1, %2;" : "=l"(ud) : "l"(ua), "l"(ub));
    return *(float2*)&ud;
}

// ---------------- tf32 helpers ----------------
__device__ __forceinline__ float tf32_rna(float x) {
    unsigned u;
    asm("cvt.rna.tf32.f32 %0, %1;" : "=r"(u) : "f"(x));
    return __uint_as_float(u);
}
// D(16x8) += A(16x8k) * B(8k x 8n);  a,b given as tf32-valued floats
__device__ __forceinline__ void mma_tf32(float* d, const float* a, const float* b) {
    asm("mma.sync.aligned.m16n8k8.row.col.f32.tf32.tf32.f32 "
        "{%0,%1,%2,%3}, {%4,%5,%6,%7}, {%8,%9}, {%0,%1,%2,%3};"
        : "+f"(d[0]), "+f"(d[1]), "+f"(d[2]), "+f"(d[3])
        : "r"(__float_as_uint(a[0])), "r"(__float_as_uint(a[1])),
          "r"(__float_as_uint(a[2])), "r"(__float_as_uint(a[3])),
          "r"(__float_as_uint(b[0])), "r"(__float_as_uint(b[1])));
}

__device__ __forceinline__ float atanh_c(float x) {
    x = fminf(fmaxf(x, -0.9999999f), 0.9999999f);
    return atanhf(x);
}
__device__ __forceinline__ float dot4(float4 a, float4 b) {
    return a.x * b.x + a.y * b.y + a.z * b.z + a.w * b.w;
}
__device__ __forceinline__ float warpsum(float v) {
    #pragma unroll
    for (int o = 16; o; o >>= 1) v += __shfl_xor_sync(0xffffffffu, v, o);
    return v;
}
__device__ __forceinline__ float grp4sum(float v) {
    v += __shfl_xor_sync(0xffffffffu, v, 1, 4);
    v += __shfl_xor_sync(0xffffffffu, v, 2, 4);
    return v;
}
__device__ __forceinline__ float blkred(float v, float* sm) {
    #pragma unroll
    for (int o = 16; o; o >>= 1) v += __shfl_xor_sync(0xffffffffu, v, o);
    if ((threadIdx.x & 31) == 0) sm[threadIdx.x >> 5] = v;
    __syncthreads();
    v = sm[0] + sm[1] + sm[2] + sm[3];
    __syncthreads();
    return v;
}

// ===== K0: split inputs into tf32 hi/lo planes (A rows pre-permuted) =====
__global__ __launch_bounds__(256) void convert_kernel(
    const float* __restrict__ query,
    const float* __restrict__ Wq,
    const float* __restrict__ Wk,
    const float* __restrict__ Wv)
{
    int gid = blockIdx.x * 256 + threadIdx.x;   // float4 id, total 262144
    float4 v;
    float *oh, *ol;
    int oi;
    if (gid < 65536) {                          // A = permuted query
        int row = gid >> 7, c4 = gid & 127;     // out row r = b*256+s'
        int ir = ((row & 255) << 1) + (row >> 8);  // in row s'*2+b
        v = *(const float4*)(query + (ir << 9) + (c4 << 2));
        oh = g_ah; ol = g_al; oi = gid;
    } else {                                    // B mats, direct
        int g2 = gid - 65536;
        int mat = g2 >> 16, w = g2 & 65535;
        const float* W = (mat == 0) ? Wq : (mat == 1 ? Wk : Wv);
        v = *(const float4*)(W + (w << 2));
        oh = g_bh; ol = g_bl; oi = g2;
    }
    float4 h, l;
    h.x = tf32_rna(v.x); l.x = tf32_rna(v.x - h.x);
    h.y = tf32_rna(v.y); l.y = tf32_rna(v.y - h.y);
    h.z = tf32_rna(v.z); l.z = tf32_rna(v.z - h.z);
    h.w = tf32_rna(v.w); l.w = tf32_rna(v.w - h.w);
    ((float4*)oh)[oi] = h;
    ((float4*)ol)[oi] = l;
}

// ===== K1: tf32 tensor-core GEMM, hi/lo 3-product split =====
// out[r][n] = sum_k A[r][k] * W[n][k];  64x64 tile, 8 warps = 4(m) x 2(n)
__global__ __launch_bounds__(256) void gemm_tc_kernel()
{
    __shared__ __align__(16) float Ah[64 * 36];
    __shared__ __align__(16) float Al[64 * 36];
    __shared__ __align__(16) float Bh[64 * 36];
    __shared__ __align__(16) float Bl[64 * 36];
    int mat = blockIdx.z;
    int m0 = blockIdx.y << 6, n0 = blockIdx.x << 6;
    int t = threadIdx.x, lane = t & 31, wid = t >> 5;
    int wm = (wid & 3) << 4;            // warp m offset (16 rows)
    int wn = (wid >> 2) << 5;           // warp n offset (32 cols)
    int g = lane >> 2, tig = lane & 3;
    const float* pBh = g_bh + (mat << 18);
    const float* pBl = g_bl + (mat << 18);
    float* out = g_mx + mat * NROW * HIDD;

    float acc[4][4];
    #pragma unroll
    for (int i = 0; i < 4; i++)
        #pragma unroll
        for (int j = 0; j < 4; j++) acc[i][j] = 0.f;

    for (int k0 = 0; k0 < HIDD; k0 += 32) {
        __syncthreads();
        for (int li = t; li < 512; li += 256) {
            int row = li >> 3, c4 = li & 7;
            int so = row * 36 + (c4 << 2);
            int ga = ((m0 + row) << 9) + k0 + (c4 << 2);
            int gb = ((n0 + row) << 9) + k0 + (c4 << 2);
            *(float4*)&Ah[so] = *(const float4*)(g_ah + ga);
            *(float4*)&Al[so] = *(const float4*)(g_al + ga);
            *(float4*)&Bh[so] = *(const float4*)(pBh + gb);
            *(float4*)&Bl[so] = *(const float4*)(pBl + gb);
        }
        __syncthreads();
        #pragma unroll
        for (int ks = 0; ks < 4; ks++) {
            int k = ks << 3;
            int ra = (wm + g) * 36 + k + tig;
            int rb = (wm + g + 8) * 36 + k + tig;
            float ah[4], al[4];
            ah[0] = Ah[ra];     ah[1] = Ah[rb];
            ah[2] = Ah[ra + 4]; ah[3] = Ah[rb + 4];
            al[0] = Al[ra];     al[1] = Al[rb];
            al[2] = Al[ra + 4]; al[3] = Al[rb + 4];
            #pragma unroll
            for (int nt = 0; nt < 4; nt++) {
                int n = wn + (nt << 3) + g;
                int ob = n * 36 + k + tig;
                float bh[2] = {Bh[ob], Bh[ob + 4]};
                float bl[2] = {Bl[ob], Bl[ob + 4]};
                mma_tf32(acc[nt], ah, bh);
                mma_tf32(acc[nt], ah, bl);
                mma_tf32(acc[nt], al, bh);
            }
        }
    }
    int r0 = m0 + wm + g;
    #pragma unroll
    for (int nt = 0; nt < 4; nt++) {
        int col = n0 + wn + (nt << 3) + (tig << 1);
        *(float2*)(out + (r0 << 9) + col)       = make_float2(acc[nt][0], acc[nt][1]);
        *(float2*)(out + ((r0 + 8) << 9) + col) = make_float2(acc[nt][2], acc[nt][3]);
    }
}

// ===== K2: warp-per-row epilogue — shuffle-only reductions =====
__global__ __launch_bounds__(256) void epilogue_kernel(
    const float* __restrict__ query,
    const float* __restrict__ bq,
    const float* __restrict__ bk,
    const float* __restrict__ bv)
{
    int w = blockIdx.x * 8 + (threadIdx.x >> 5);   // global warp = row task
    int l = threadIdx.x & 31;
    int mat = w >> 9;            // 0..2
    int r = w & 511;             // b*256 + s'
    int b = r >> 8, sp = r & 255;
    const float* bias_p = (mat == 0) ? bq : (mat == 1 ? bk : bv);
    float* outp = (mat == 0) ? g_q : (mat == 1 ? g_k : g_v);

    const float4* xp = (const float4*)(query + ((sp * BATCH + b) << 9));
    const float4* mp = (const float4*)(g_mx + mat * NROW * HIDD + (r << 9));
    const float4* bp = (const float4*)bias_p;

    float4 x4[4], m4[4], bi4[4];
    #pragma unroll
    for (int j = 0; j < 4; j++) {
        x4[j]  = xp[4 * l + j];
        m4[j]  = mp[4 * l + j];
        bi4[j] = bp[4 * l + j];
    }

    float sxx = 0.f, smm = 0.f;
    #pragma unroll
    for (int j = 0; j < 4; j++) { sxx += dot4(x4[j], x4[j]); smm += dot4(m4[j], m4[j]); }
    sxx = warpsum(sxx);
    smm = warpsum(smm);
    float xn = fmaxf(sqrtf(sxx), EPSN);
    float mn = fmaxf(sqrtf(smm), EPSN);
    float sc1 = tanhf(mn / xn * atanh_c(xn)) / mn;

    float4 res[4];
    float x2 = 0.f, xy = 0.f, y2 = 0.f;
    #pragma unroll
    for (int j = 0; j < 4; j++) {
        res[j] = make_float4(sc1 * m4[j].x, sc1 * m4[j].y, sc1 * m4[j].z, sc1 * m4[j].w);
        x2 += dot4(res[j], res[j]);
        xy += dot4(res[j], bi4[j]);
        y2 += dot4(bi4[j], bi4[j]);
    }
    x2 = warpsum(x2); xy = warpsum(xy); y2 = warpsum(y2);
    float ac = 1.f + 2.f * xy + y2;
    float bc = 1.f - x2;
    float den = fmaxf(1.f + 2.f * xy + x2 * y2, EPSN);
    float idn = 1.f / den;

    float4 z4[4];
    float z2 = 0.f;
    #pragma unroll
    for (int j = 0; j < 4; j++) {
        z4[j] = make_float4((ac * res[j].x + bc * bi4[j].x) * idn,
                            (ac * res[j].y + bc * bi4[j].y) * idn,
                            (ac * res[j].z + bc * bi4[j].z) * idn,
                            (ac * res[j].w + bc * bi4[j].w) * idn);
        z2 += dot4(z4[j], z4[j]);
    }
    z2 = warpsum(z2);
    float nz = fmaxf(sqrtf(z2), EPSN);
    float ps = (nz > MAXNORM) ? (MAXNORM / nz) : 1.f;
    float nzc = nz * ps;                       // = min(nz, MAXNORM)
    float us = atanh_c(nzc) / fmaxf(nzc, EPSN) * ps;   // u = us * z

    float4 u4[4];
    float cs = 0.f;
    #pragma unroll
    for (int j = 0; j < 4; j++) {
        u4[j] = make_float4(us * z4[j].x, us * z4[j].y, us * z4[j].z, us * z4[j].w);
        cs += dot4(u4[j], u4[j]);
    }
    cs = grp4sum(cs);                          // 64-elem chunk = 4 lanes
    float cn = fmaxf(sqrtf(cs), EPSN);
    float csc = tanhf(cn) / cn;

    float4* op = (float4*)(outp + (r << 9));
    #pragma unroll
    for (int j = 0; j < 4; j++)
        op[4 * l + j] = make_float4(csc * u4[j].x, csc * u4[j].y, csc * u4[j].z, csc * u4[j].w);

    if ((l & 3) == 0) {
        float o2 = csc * csc * cs;             // |chunk|^2 of output
        int cid = b * CHB + sp * 8 + (l >> 2); // flat chunk id == h*256+s
        if (mat == 0)      g_q2[cid] = o2;
        else if (mat == 1) g_k2[cid] = o2;
        else               g_gamma[cid] = 2.f / fmaxf(1.f - o2, EPSN);
    }
}

// ===== K3 (fused): scores -> probs + midpoint partial, 32q x 64n tile =====
// Phase A packed-f32x2 + Bc factoring (identical math to R14).
__global__ __launch_bounds__(256, 2) void score_ctx_kernel(float* __restrict__ probs_ext)
{
    __shared__ float regA[32 * 68];   // qsm (32x64, str 68) -> psm (32x65)
    __shared__ float regB[64 * 68];   // ksm -> (gamma*v) as float4[64][17]
    __shared__ float q2s[32];
    __shared__ float k2s[64];
    __shared__ float gm1[64];
    float* probs = probs_ext ? probs_ext : g_probs;

    int bh = blockIdx.z;
    int b = bh >> 3, h = bh & 7;
    int q0 = blockIdx.y << 5, n0 = blockIdx.x << 6;
    int ns = blockIdx.x;               // n-split id for partials
    const float4* Qp = (const float4*)(g_q + b * 131072 + ((h << 8) + q0) * 64);
    const float4* Kp = (const float4*)(g_k + b * 131072 + ((h << 8) + n0) * 64);
    int t = threadIdx.x;

    for (int li = t; li < 1024; li += 256) {
        int row = li >> 4, c4 = li & 15;
        *(float4*)&regB[row * 68 + (c4 << 2)] = Kp[li];
    }
    for (int li = t; li < 512; li += 256) {
        int row = li >> 4, c4 = li & 15;
        *(float4*)&regA[row * 68 + (c4 << 2)] = Qp[li];
    }
    if (t < 32) q2s[t] = g_q2[b * CHB + (h << 8) + q0 + t];
    if (t < 64) k2s[t] = g_k2[b * CHB + (h << 8) + n0 + t];
    __syncthreads();

    int qi = t >> 3, nl = t & 7;
    float4 qr[16];
    #pragma unroll
    for (int i = 0; i < 16; i++) qr[i] = *(const float4*)&regA[qi * 68 + (i << 2)];
    float q2 = q2s[qi];
    float Bc = 1.f - q2;
    float invBc = 1.f / Bc;
    float* orow = probs + ((bh << 8) + q0 + qi) * 256 + n0;
    __syncthreads();                   // all qr loaded; regA may be overwritten

    #pragma unroll 1
    for (int jj = 0; jj < 4; jj++) {
        int na = (jj << 4) | nl;       // two n per iteration: na, na+8
        int nb = na + 8;
        // ---- pass 1: dot products, packed (4 independent chains) ----
        float2 sa0 = make_float2(0.f, 0.f), sa1 = make_float2(0.f, 0.f);
        float2 sb0 = make_float2(0.f, 0.f), sb1 = make_float2(0.f, 0.f);
        #pragma unroll
        for (int i = 0; i < 16; i++) {
            float4 q = qr[i];
            float4 ka = *(const float4*)&regB[na * 68 + (i << 2)];
            float4 kb = *(const float4*)&regB[nb * 68 + (i << 2)];
            sa0 = ffma2(make_float2(q.x, q.y), make_float2(ka.x, ka.y), sa0);
            sa1 = ffma2(make_float2(q.z, q.w), make_float2(ka.z, ka.w), sa1);
            sb0 = ffma2(make_float2(q.x, q.y), make_float2(kb.x, kb.y), sb0);
            sb1 = ffma2(make_float2(q.z, q.w), make_float2(kb.z, kb.w), sb1);
        }
        float da = sa0.x + sa0.y + sa1.x + sa1.y;
        float db = sb0.x + sb0.y + sb1.x + sb1.y;
        float k2a = k2s[na], k2b = k2s[nb];
        float Aa = 1.f - 2.f * da + k2a;
        float Ab = 1.f - 2.f * db + k2b;
        float dena = fmaxf(fmaf(q2, k2a, 1.f - 2.f * da), EPSN);
        float denb = fmaxf(fmaf(q2, k2b, 1.f - 2.f * db), EPSN);
        float ra = Aa * invBc;
        float rb = Ab * invBc;
        float2 mra = make_float2(-ra, -ra);
        float2 mrb = make_float2(-rb, -rb);
        // ---- pass 2: sum of reciprocal squares, packed quad-combine ----
        float acca = 0.f, accb = 0.f;
        #pragma unroll
        for (int i = 0; i < 16; i++) {
            float4 q = qr[i];
            float2 q01 = make_float2(q.x, q.y);
            float2 q23 = make_float2(q.z, q.w);
            float4 ka = *(const float4*)&regB[na * 68 + (i << 2)];
            float4 kb = *(const float4*)&regB[nb * 68 + (i << 2)];
            {
                float2 w01 = ffma2(mra, q01, make_float2(ka.x, ka.y));  // k - r*q
                float2 w23 = ffma2(mra, q23, make_float2(ka.z, ka.w));
                float2 x01 = fmul2(w01, w01);
                float2 x23 = fmul2(w23, w23);
                float2 s2 = fadd2(x01, x23);
                float2 p2 = fmul2(x01, x23);
                float num = fmaf(s2.x, p2.y, s2.y * p2.x);
                float dn4 = fmaxf(p2.x * p2.y, 1e-37f);
                acca += __fdividef(num, dn4);
            }
            {
                float2 w01 = ffma2(mrb, q01, make_float2(kb.x, kb.y));
                float2 w23 = ffma2(mrb, q23, make_float2(kb.z, kb.w));
                float2 x01 = fmul2(w01, w01);
                float2 x23 = fmul2(w23, w23);
                float2 s2 = fadd2(x01, x23);
                float2 p2 = fmul2(x01, x23);
                float num = fmaf(s2.x, p2.y, s2.y * p2.x);
                float dn4 = fmaxf(p2.x * p2.y, 1e-37f);
                accb += __fdividef(num, dn4);
            }
        }
        float t1a = __fdividef(Bc * rsqrtf(acca), dena);
        float t1b = __fdividef(Bc * rsqrtf(accb), denb);
        t1a = fminf(t1a, 0.9999999f);
        t1b = fminf(t1b, 0.9999999f);
        float pa = 0.5f - 0.5f * t1a;
        float pb = 0.5f - 0.5f * t1b;
        orow[na] = pa;
        orow[nb] = pb;
        regA[qi * 65 + na] = pa;       // psm (32x65, aliases qsm region)
        regA[qi * 65 + nb] = pb;
    }
    __syncthreads();                   // probs tile complete; ksm no longer needed

    // ---- load gamma*v into regB as float4[64][17]; gm1 ----
    {
        const float* Vb  = g_v + b * 131072 + (h << 14);
        const float* gmb = g_gamma + b * CHB + (h << 8);
        for (int li = t; li < 1024; li += 256) {
            int n = li >> 4, d4 = li & 15;
            int gn = n0 + n;
            float g = gmb[gn];
            float4 v = *(const float4*)(Vb + (gn << 6) + (d4 << 2));
            ((float4*)regB)[n * 17 + d4] = make_float4(v.x * g, v.y * g, v.z * g, v.w * g);
        }
        if (t < 64) gm1[t] = gmb[n0 + t] - 1.f;
    }
    __syncthreads();

    // ---- phase B: 2 q-rows x float4-of-d per thread ----
    int qi2 = t >> 4, dh = t & 15;
    float4 acc[2];
    float dac[2];
    #pragma unroll
    for (int j = 0; j < 2; j++) { acc[j] = make_float4(0.f, 0.f, 0.f, 0.f); dac[j] = 0.f; }

    #pragma unroll 4
    for (int n = 0; n < 64; n++) {
        float4 v = ((const float4*)regB)[n * 17 + dh];
        float g1 = gm1[n];
        #pragma unroll
        for (int j = 0; j < 2; j++) {
            float p = regA[(qi2 + (j << 4)) * 65 + n];
            acc[j].x = fmaf(p, v.x, acc[j].x);
            acc[j].y = fmaf(p, v.y, acc[j].y);
            acc[j].z = fmaf(p, v.z, acc[j].z);
            acc[j].w = fmaf(p, v.w, acc[j].w);
            dac[j] = fmaf(p, g1, dac[j]);
        }
    }
    #pragma unroll
    for (int j = 0; j < 2; j++) {
        int row = (b << 8) + q0 + qi2 + (j << 4);
        *(float4*)(g_pnom + ((ns * NROW + row) << 9) + (h << 6) + (dh << 2)) = acc[j];
        if (dh == 0)
            g_pdac[((ns * NROW + row) << 3) + h] = dac[j];
    }
}

// ===== K5: reduce partials + gyro epilogue + final expmap0 + transpose =====
__global__ __launch_bounds__(128) void final_kernel(float* __restrict__ out)
{
    __shared__ float red[4];
    int row = blockIdx.x;          // b*256 + q
    int b = row >> 8, q = row & 255;
    int t = threadIdx.x;
    int h = t >> 4;

    float4 nom = {0.f, 0.f, 0.f, 0.f};
    float dacc = 0.f;
    #pragma unroll
    for (int ns = 0; ns < 4; ns++) {
        float4 pv = *(const float4*)(g_pnom + ((ns * NROW + row) << 9) + (t << 2));
        nom.x += pv.x; nom.y += pv.y; nom.z += pv.z; nom.w += pv.w;
        dacc += g_pdac[((ns * NROW + row) << 3) + h];
    }

    float dn = fmaxf(fabsf(dacc), 1e-10f);
    if (dacc < 0.f) dn = -dn;
    float idn = 1.f / dn;
    float4 c0 = {nom.x * idn, nom.y * idn, nom.z * idn, nom.w * idn};
    float ss = dot4(c0, c0);
    #pragma unroll
    for (int o = 8; o; o >>= 1) ss += __shfl_xor_sync(0xffffffffu, ss, o, 16);
    float nn = fmaxf(sqrtf(ss), EPSN);
    float usc = 0.5f * atanh_c(nn) / nn;
    float4 u = {usc * c0.x, usc * c0.y, usc * c0.z, usc * c0.w};

    float s = blkred(dot4(u, u), red);
    float n512 = fmaxf(sqrtf(s), EPSN);
    float sc = tanhf(n512) / n512;
    float4 o = {sc * u.x, sc * u.y, sc * u.z, sc * u.w};
    *(float4*)(out + ((q * BATCH + b) << 9) + (t << 2)) = o;
}

// ---------------- launch ----------------
extern "C" void kernel_launch(void* const* d_in, const int* in_sizes, int n_in,
                              void* d_out, int out_size)
{
    const float* query = (const float*)d_in[0];
    const float* Wq = (const float*)d_in[1];
    const float* bq = (const float*)d_in[2];
    const float* Wk = (const float*)d_in[3];
    const float* bk = (const float*)d_in[4];
    const float* Wv = (const float*)d_in[5];
    const float* bv = (const float*)d_in[6];
    float* out = (float*)d_out;

    // output layout: ctx [S,B,HID] (262144) then probs [B,H,S,S] (1048576)
    float* probs = (out_size >= 262144 + 1048576) ? (out + 262144) : (float*)0;

    convert_kernel<<<1024, 256>>>(query, Wq, Wk, Wv);
    gemm_tc_kernel<<<dim3(8, 8, 3), 256>>>();
    epilogue_kernel<<<192, 256>>>(query, bq, bk, bv);
    score_ctx_kernel<<<dim3(4, 8, 16), 256>>>(probs);
    final_kernel<<<512, 128>>>(out);
}